// round 3
// baseline (speedup 1.0000x reference)
#include <cuda_runtime.h>
#include <math.h>

#define N_NODES 3072
#define F_IN 512
#define NHID 64
#define NHEADS 4
#define NGRAPH 3
#define NCLASS 16
#define NGH (NGRAPH * NHEADS)
#define DCAT (NHEADS * NHID)   // 256
#define ALPHA 0.2f
#define NEG_INF_F (-9000000000000000.0f)

// -------- scratch (no allocations allowed) --------
__device__ float d_Wh[NGH * N_NODES * NHID];           // 9.4 MB  [gh][n][o]
__device__ float d_f1[NGH * N_NODES];
__device__ float d_f2[NGH * N_NODES];
__device__ float d_hcat[NGRAPH * N_NODES * DCAT];      // 9.4 MB  [g][n][h*64+o]

// ============================================================
// K1: Wh[gh] = x @ W[gh]   (3072x512 @ 512x64), fp32 tiled
// grid (48, 12), 256 threads. 64x64 tile, K-tile 32.
// ============================================================
__global__ __launch_bounds__(256) void k1_wh(const float* __restrict__ x,
                                             const float* __restrict__ W) {
    __shared__ float xs[64][33];   // pad 33 -> bank = (r+kk)%32
    __shared__ float ws[32][64];
    const int gh = blockIdx.y;
    const int n0 = blockIdx.x * 64;
    const int t  = threadIdx.x;
    const int ty = t >> 4, tx = t & 15;

    const float* Wg = W + (size_t)gh * F_IN * NHID;
    float acc[4][4];
#pragma unroll
    for (int i = 0; i < 4; i++)
#pragma unroll
        for (int j = 0; j < 4; j++) acc[i][j] = 0.f;

    for (int k0 = 0; k0 < F_IN; k0 += 32) {
#pragma unroll
        for (int q = 0; q < 2; q++) {
            int idx = t + q * 256;              // 0..511
            int r = idx >> 3, k4 = (idx & 7) * 4;
            float4 v = *(const float4*)(x + (size_t)(n0 + r) * F_IN + k0 + k4);
            xs[r][k4 + 0] = v.x; xs[r][k4 + 1] = v.y;
            xs[r][k4 + 2] = v.z; xs[r][k4 + 3] = v.w;
        }
#pragma unroll
        for (int q = 0; q < 2; q++) {
            int idx = t + q * 256;
            int r = idx >> 4, o4 = (idx & 15) * 4;
            *(float4*)(&ws[r][o4]) = *(const float4*)(Wg + (size_t)(k0 + r) * NHID + o4);
        }
        __syncthreads();
#pragma unroll
        for (int kk = 0; kk < 32; kk++) {
            float a_[4];
#pragma unroll
            for (int i = 0; i < 4; i++) a_[i] = xs[ty * 4 + i][kk];
            float4 bv = *(float4*)(&ws[kk][tx * 4]);
#pragma unroll
            for (int i = 0; i < 4; i++) {
                acc[i][0] += a_[i] * bv.x; acc[i][1] += a_[i] * bv.y;
                acc[i][2] += a_[i] * bv.z; acc[i][3] += a_[i] * bv.w;
            }
        }
        __syncthreads();
    }
    float* out = d_Wh + (size_t)gh * N_NODES * NHID;
#pragma unroll
    for (int i = 0; i < 4; i++) {
        float4 v = make_float4(acc[i][0], acc[i][1], acc[i][2], acc[i][3]);
        *(float4*)(out + (size_t)(n0 + ty * 4 + i) * NHID + tx * 4) = v;
    }
}

// ============================================================
// K1b: f1/f2 = Wh . a1 / a2   (one warp per (gh,n) row)
// grid 4608, 256 threads (8 warps)
// ============================================================
__global__ __launch_bounds__(256) void k1_f(const float* __restrict__ a) {
    const int w = threadIdx.x >> 5, lane = threadIdx.x & 31;
    const int row = blockIdx.x * 8 + w;          // 0..36863  == gh*N + n
    const int gh = row / N_NODES;
    const float* whrow = d_Wh + (size_t)row * NHID;
    const float* ag = a + (size_t)gh * 2 * NHID;
    float w0 = whrow[lane], w1 = whrow[lane + 32];
    float s1 = w0 * ag[lane] + w1 * ag[lane + 32];
    float s2 = w0 * ag[64 + lane] + w1 * ag[96 + lane];
#pragma unroll
    for (int off = 16; off > 0; off >>= 1) {
        s1 += __shfl_xor_sync(0xffffffffu, s1, off);
        s2 += __shfl_xor_sync(0xffffffffu, s2, off);
    }
    if (lane == 0) { d_f1[row] = s1; d_f2[row] = s2; }
}

// ============================================================
// K2: fused masked-softmax attention + P@Wh + ELU
// one block per (g, h, 64-row tile); loops over 48 m-tiles of 64.
// Online softmax: per-thread state for 4 rows, shuffle-reduced
// across the 16-thread tx group (lanes 0-15 / 16-31 of a warp).
// ============================================================
__global__ __launch_bounds__(256) void k2_attn(const int* __restrict__ adj) {
    __shared__ float Whs[64 * 64];
    __shared__ float ps[64 * 65];    // stride 65 -> bank=(r+kk)%32, 2-way max
    const int g = blockIdx.z, h = blockIdx.y;
    const int gh = g * NHEADS + h;
    const int n0 = blockIdx.x * 64;
    const int t = threadIdx.x, ty = t >> 4, tx = t & 15;

    const float* Whg = d_Wh + (size_t)gh * N_NODES * NHID;
    const int*   adjg = adj + (size_t)g * N_NODES * N_NODES;
    const float* f2g = d_f2 + (size_t)gh * N_NODES;

    float f1r[4];
#pragma unroll
    for (int i = 0; i < 4; i++) f1r[i] = d_f1[(size_t)gh * N_NODES + n0 + ty * 4 + i];

    float rmax[4], rsum[4], acc[4][4];
#pragma unroll
    for (int i = 0; i < 4; i++) {
        rmax[i] = -INFINITY; rsum[i] = 0.f;
#pragma unroll
        for (int j = 0; j < 4; j++) acc[i][j] = 0.f;
    }

    for (int m0 = 0; m0 < N_NODES; m0 += 64) {
        __syncthreads();   // protect smem from previous iteration's readers
        // load Wh m-tile [64 x 64]
#pragma unroll
        for (int q = 0; q < 4; q++) {
            int idx = t + q * 256;
            int r = idx >> 4, o4 = (idx & 15) * 4;
            *(float4*)(Whs + r * 64 + o4) =
                *(const float4*)(Whg + (size_t)(m0 + r) * NHID + o4);
        }
        // scores (registers)
        float4 f2v = *(const float4*)(f2g + m0 + tx * 4);
        float f2a[4] = { f2v.x, f2v.y, f2v.z, f2v.w };
        float p[4][4], tmax[4];
#pragma unroll
        for (int i = 0; i < 4; i++) {
            int4 av = *(const int4*)(adjg + (size_t)(n0 + ty * 4 + i) * N_NODES + m0 + tx * 4);
            int am[4] = { av.x, av.y, av.z, av.w };
            float mx = -INFINITY;
#pragma unroll
            for (int j = 0; j < 4; j++) {
                float tv = f1r[i] + f2a[j];
                tv = tv > 0.f ? tv : ALPHA * tv;
                float s = (am[j] > 0) ? tv : NEG_INF_F;
                p[i][j] = s;
                mx = fmaxf(mx, s);
            }
            tmax[i] = mx;
        }
        // tile max across tx group (xor 1,2,4,8 stays in 16-lane halves)
#pragma unroll
        for (int off = 1; off < 16; off <<= 1)
#pragma unroll
            for (int i = 0; i < 4; i++)
                tmax[i] = fmaxf(tmax[i], __shfl_xor_sync(0xffffffffu, tmax[i], off));

        float lsum[4];
#pragma unroll
        for (int i = 0; i < 4; i++) {
            float nm = fmaxf(rmax[i], tmax[i]);
            float sc = __expf(rmax[i] - nm);
            rmax[i] = nm;
            float ls = 0.f;
#pragma unroll
            for (int j = 0; j < 4; j++) {
                float e = __expf(p[i][j] - nm);
                p[i][j] = e; ls += e;
            }
            lsum[i] = ls;
#pragma unroll
            for (int j = 0; j < 4; j++) acc[i][j] *= sc;
            rsum[i] *= sc;
        }
#pragma unroll
        for (int off = 1; off < 16; off <<= 1)
#pragma unroll
            for (int i = 0; i < 4; i++)
                lsum[i] += __shfl_xor_sync(0xffffffffu, lsum[i], off);
#pragma unroll
        for (int i = 0; i < 4; i++) rsum[i] += lsum[i];

        // stage p
#pragma unroll
        for (int i = 0; i < 4; i++)
#pragma unroll
            for (int j = 0; j < 4; j++)
                ps[(ty * 4 + i) * 65 + tx * 4 + j] = p[i][j];
        __syncthreads();

        // acc += p @ Wh_tile
#pragma unroll 4
        for (int kk = 0; kk < 64; kk++) {
            float4 bv = *(float4*)(Whs + kk * 64 + tx * 4);
            float a0 = ps[(ty * 4 + 0) * 65 + kk];
            float a1 = ps[(ty * 4 + 1) * 65 + kk];
            float a2 = ps[(ty * 4 + 2) * 65 + kk];
            float a3 = ps[(ty * 4 + 3) * 65 + kk];
            acc[0][0] += a0 * bv.x; acc[0][1] += a0 * bv.y; acc[0][2] += a0 * bv.z; acc[0][3] += a0 * bv.w;
            acc[1][0] += a1 * bv.x; acc[1][1] += a1 * bv.y; acc[1][2] += a1 * bv.z; acc[1][3] += a1 * bv.w;
            acc[2][0] += a2 * bv.x; acc[2][1] += a2 * bv.y; acc[2][2] += a2 * bv.z; acc[2][3] += a2 * bv.w;
            acc[3][0] += a3 * bv.x; acc[3][1] += a3 * bv.y; acc[3][2] += a3 * bv.z; acc[3][3] += a3 * bv.w;
        }
    }

    // epilogue: normalize, ELU, write [g][n][h*64+o]
    float* outg = d_hcat + (size_t)g * N_NODES * DCAT;
#pragma unroll
    for (int i = 0; i < 4; i++) {
        float inv = 1.0f / rsum[i];
        float v[4];
#pragma unroll
        for (int j = 0; j < 4; j++) {
            float hv = acc[i][j] * inv;
            v[j] = hv > 0.f ? hv : (__expf(hv) - 1.0f);
        }
        *(float4*)(outg + (size_t)(n0 + ty * 4 + i) * DCAT + h * NHID + tx * 4) =
            make_float4(v[0], v[1], v[2], v[3]);
    }
}

// ============================================================
// K3: xi = elu(hcat @ W_int^T + b_int); fuse -> out @ W_fus^T + b_fus
//     -> log_softmax.  One warp per node row.
// grid 768, 128 threads (4 warps)
// ============================================================
__global__ __launch_bounds__(128) void k3_out(const float* __restrict__ Wint,
                                              const float* __restrict__ bint,
                                              const float* __restrict__ Wfus,
                                              const float* __restrict__ bfus,
                                              float* __restrict__ out) {
    __shared__ float sWi[NCLASS * DCAT];          // 16x256
    __shared__ float sWf[NCLASS * (NCLASS * NGRAPH)];  // 16x48
    __shared__ float sbi[NCLASS], sbf[NCLASS];
    const int t = threadIdx.x;
    for (int i = t; i < NCLASS * DCAT; i += 128) sWi[i] = Wint[i];
    for (int i = t; i < NCLASS * NCLASS * NGRAPH; i += 128) sWf[i] = Wfus[i];
    if (t < NCLASS) { sbi[t] = bint[t]; sbf[t] = bfus[t]; }
    __syncthreads();

    const int w = t >> 5, lane = t & 31;
    const int n = blockIdx.x * 4 + w;

    float r[NGRAPH][8];
#pragma unroll
    for (int g = 0; g < NGRAPH; g++)
#pragma unroll
        for (int k = 0; k < 8; k++)
            r[g][k] = d_hcat[(size_t)g * N_NODES * DCAT + (size_t)n * DCAT + lane + 32 * k];

    float xi[48];
#pragma unroll
    for (int j = 0; j < 48; j++) {
        int g = j >> 4, c = j & 15;
        float s = 0.f;
#pragma unroll
        for (int k = 0; k < 8; k++) s += r[g][k] * sWi[c * DCAT + lane + 32 * k];
#pragma unroll
        for (int off = 16; off > 0; off >>= 1)
            s += __shfl_xor_sync(0xffffffffu, s, off);
        s += sbi[c];
        xi[j] = s > 0.f ? s : (__expf(s) - 1.0f);
    }

    int cc = lane & 15;
    float o = sbf[cc];
#pragma unroll
    for (int j = 0; j < 48; j++) o += xi[j] * sWf[cc * 48 + j];

    float m = o;
#pragma unroll
    for (int off = 1; off < 16; off <<= 1)
        m = fmaxf(m, __shfl_xor_sync(0xffffffffu, m, off));
    float e = __expf(o - m), se = e;
#pragma unroll
    for (int off = 1; off < 16; off <<= 1)
        se += __shfl_xor_sync(0xffffffffu, se, off);
    float lp = o - m - logf(se);
    if (lane < 16) out[(size_t)n * NCLASS + cc] = lp;
}

// ============================================================
// K4: l1 loss = mean |W_fus|
// ============================================================
__global__ void k4_loss(const float* __restrict__ Wfus, float* __restrict__ out) {
    __shared__ float s[256];
    const int t = threadIdx.x;
    float v = 0.f;
    for (int i = t; i < NCLASS * NCLASS * NGRAPH; i += 256) v += fabsf(Wfus[i]);
    s[t] = v;
    __syncthreads();
    for (int st = 128; st > 0; st >>= 1) {
        if (t < st) s[t] += s[t + st];
        __syncthreads();
    }
    if (t == 0) out[N_NODES * NCLASS] = s[0] / (float)(NCLASS * NCLASS * NGRAPH);
}

// ============================================================
extern "C" void kernel_launch(void* const* d_in, const int* in_sizes, int n_in,
                              void* d_out, int out_size) {
    const float* x    = (const float*)d_in[0];
    const int*   adj  = (const int*)  d_in[1];
    const float* W    = (const float*)d_in[2];
    const float* a    = (const float*)d_in[3];
    const float* Wint = (const float*)d_in[4];
    const float* bint = (const float*)d_in[5];
    const float* Wfus = (const float*)d_in[6];
    const float* bfus = (const float*)d_in[7];
    float* out = (float*)d_out;

    k1_wh<<<dim3(N_NODES / 64, NGH), 256>>>(x, W);
    k1_f<<<NGH * N_NODES / 8, 256>>>(a);
    k2_attn<<<dim3(N_NODES / 64, NHEADS, NGRAPH), 256>>>(adj);
    k3_out<<<N_NODES / 4, 128>>>(Wint, bint, Wfus, bfus, out);
    if (out_size > N_NODES * NCLASS)
        k4_loss<<<1, 256>>>(Wfus, out);
}

// round 6
// speedup vs baseline: 3.7649x; 3.7649x over previous
#include <cuda_runtime.h>
#include <math.h>
#include <stdint.h>

#define N_NODES 3072
#define F_IN 512
#define NHID 64
#define NHEADS 4
#define NGRAPH 3
#define NCLASS 16
#define NGH (NGRAPH * NHEADS)
#define DCAT (NHEADS * NHID)   // 256
#define ALPHA 0.2f
#define NEG_INF_F (-9000000000000000.0f)

// -------- scratch (no allocations allowed) --------
__device__ float d_Wh[NGH * N_NODES * NHID];                 // [gh][n][o]
__device__ float d_f1[NGH * N_NODES];
__device__ float d_f2[NGH * N_NODES];
__device__ float d_hcat[NGRAPH * N_NODES * DCAT];            // [g][n][h*64+o]
__device__ unsigned long long d_abits[NGRAPH * N_NODES * 48]; // bitpacked adj

// ---------- helpers ----------
__device__ __forceinline__ uint32_t f2tf32(float f) {
    uint32_t u;
    asm("cvt.rna.tf32.f32 %0, %1;" : "=r"(u) : "f"(f));
    return u;
}
__device__ __forceinline__ void mma_tf32(float d[4], uint32_t a0, uint32_t a1,
                                         uint32_t a2, uint32_t a3,
                                         uint32_t b0, uint32_t b1) {
    asm volatile(
        "mma.sync.aligned.m16n8k8.row.col.f32.tf32.tf32.f32 "
        "{%0,%1,%2,%3},{%4,%5,%6,%7},{%8,%9},{%0,%1,%2,%3};\n"
        : "+f"(d[0]), "+f"(d[1]), "+f"(d[2]), "+f"(d[3])
        : "r"(a0), "r"(a1), "r"(a2), "r"(a3), "r"(b0), "r"(b1));
}
// B-operand swizzle: element (k,n) of a 64x64 tile. Conflict-free for
// b-frag reads (k=8kt+q[+4], n=8nt+g): bank = g + 8*((nt&3)^q)  -> 32 distinct.
__device__ __forceinline__ int bswz(int k, int n) {
    return k * 64 + (n ^ ((k & 3) << 3));
}
// A-operand swizzle: element (r,c). Conflict-free for a-frag reads
// (r=16w+g[+8], c=8kt+q[+4]): bank = q + 4*(g>>2) + 8*((kt&3)^(g&3)).
__device__ __forceinline__ int aswz(int r, int c) {
    return r * 64 + (c ^ ((r & 3) << 3) ^ (r & 4));
}

// ============================================================
// K0: bitpack adj (int32 0/1 -> 64-bit masks). One warp per row.
// ============================================================
__global__ __launch_bounds__(256) void k0_pack(const int* __restrict__ adj) {
    const int row = blockIdx.x * 8 + (threadIdx.x >> 5);  // g*N + n
    const int lane = threadIdx.x & 31;
    const int* arow = adj + (size_t)row * N_NODES;
    unsigned long long* brow = d_abits + (size_t)row * 48;
    for (int j = 0; j < 48; j++) {
        unsigned lo = __ballot_sync(0xffffffffu, arow[j * 64 + lane] != 0);
        unsigned hi = __ballot_sync(0xffffffffu, arow[j * 64 + 32 + lane] != 0);
        if (lane == 0) brow[j] = ((unsigned long long)hi << 32) | lo;
    }
}

// ============================================================
// K1: Wh[gh] = x @ W[gh]  via tf32 mma.  grid (48,12), 128 thr (4 warps x 16 rows)
// ============================================================
__global__ __launch_bounds__(128) void k1_wh(const float* __restrict__ x,
                                             const float* __restrict__ W) {
    __shared__ uint32_t As[64 * 64];
    __shared__ uint32_t Bs[64 * 64];
    const int gh = blockIdx.y, n0 = blockIdx.x * 64;
    const int t = threadIdx.x, lane = t & 31, w = t >> 5;
    const int gi = lane >> 2, q = lane & 3;
    const float* Wg = W + (size_t)gh * F_IN * NHID;

    float acc[8][4];
#pragma unroll
    for (int nt = 0; nt < 8; nt++)
#pragma unroll
        for (int j = 0; j < 4; j++) acc[nt][j] = 0.f;

    for (int k0 = 0; k0 < F_IN; k0 += 64) {
        __syncthreads();
#pragma unroll
        for (int it = 0; it < 8; it++) {
            int idx = t + it * 128;
            int r = idx >> 4, c4 = (idx & 15) * 4;
            float4 v = *(const float4*)(x + (size_t)(n0 + r) * F_IN + k0 + c4);
            int o = aswz(r, c4);
            As[o] = f2tf32(v.x); As[o + 1] = f2tf32(v.y);
            As[o + 2] = f2tf32(v.z); As[o + 3] = f2tf32(v.w);
        }
#pragma unroll
        for (int it = 0; it < 8; it++) {
            int idx = t + it * 128;
            int k = idx >> 4, n4 = (idx & 15) * 4;
            float4 v = *(const float4*)(Wg + (size_t)(k0 + k) * NHID + n4);
            int o = bswz(k, n4);
            Bs[o] = f2tf32(v.x); Bs[o + 1] = f2tf32(v.y);
            Bs[o + 2] = f2tf32(v.z); Bs[o + 3] = f2tf32(v.w);
        }
        __syncthreads();
#pragma unroll
        for (int kt = 0; kt < 8; kt++) {
            uint32_t a0 = As[aswz(16 * w + gi,     8 * kt + q)];
            uint32_t a1 = As[aswz(16 * w + gi + 8, 8 * kt + q)];
            uint32_t a2 = As[aswz(16 * w + gi,     8 * kt + q + 4)];
            uint32_t a3 = As[aswz(16 * w + gi + 8, 8 * kt + q + 4)];
#pragma unroll
            for (int nt = 0; nt < 8; nt++) {
                uint32_t b0 = Bs[bswz(8 * kt + q,     8 * nt + gi)];
                uint32_t b1 = Bs[bswz(8 * kt + q + 4, 8 * nt + gi)];
                mma_tf32(acc[nt], a0, a1, a2, a3, b0, b1);
            }
        }
    }
    float* out = d_Wh + (size_t)gh * N_NODES * NHID;
    const int R0 = n0 + 16 * w + gi, R1 = R0 + 8;
#pragma unroll
    for (int nt = 0; nt < 8; nt++) {
        *(float2*)(out + (size_t)R0 * NHID + 8 * nt + 2 * q) =
            make_float2(acc[nt][0], acc[nt][1]);
        *(float2*)(out + (size_t)R1 * NHID + 8 * nt + 2 * q) =
            make_float2(acc[nt][2], acc[nt][3]);
    }
}

// ============================================================
// K1b: f1/f2 = Wh . a1 / a2   (one warp per (gh,n) row)
// ============================================================
__global__ __launch_bounds__(256) void k1_f(const float* __restrict__ a) {
    const int w = threadIdx.x >> 5, lane = threadIdx.x & 31;
    const int row = blockIdx.x * 8 + w;
    const int gh = row / N_NODES;
    const float* whrow = d_Wh + (size_t)row * NHID;
    const float* ag = a + (size_t)gh * 2 * NHID;
    float w0 = whrow[lane], w1 = whrow[lane + 32];
    float s1 = w0 * ag[lane] + w1 * ag[lane + 32];
    float s2 = w0 * ag[64 + lane] + w1 * ag[96 + lane];
#pragma unroll
    for (int off = 16; off > 0; off >>= 1) {
        s1 += __shfl_xor_sync(0xffffffffu, s1, off);
        s2 += __shfl_xor_sync(0xffffffffu, s2, off);
    }
    if (lane == 0) { d_f1[row] = s1; d_f2[row] = s2; }
}

// ============================================================
// K2: fused flash attention, scores in mma A-fragment layout,
// P@Wh on tf32 tensor cores. grid (48, NHEADS, NGRAPH), 128 thr.
// ============================================================
__global__ __launch_bounds__(128) void k2_attn() {
    __shared__ uint32_t Whs[2][64 * 64];  // tf32 pre-converted, B-swizzled
    __shared__ float f2s[2][64];
    const int g_ = blockIdx.z, h = blockIdx.y;
    const int gh = g_ * NHEADS + h;
    const int n0 = blockIdx.x * 64;
    const int t = threadIdx.x, lane = t & 31, w = t >> 5;
    const int gi = lane >> 2, q = lane & 3;
    const int R0 = n0 + 16 * w + gi, R1 = R0 + 8;

    const float* Whg = d_Wh + (size_t)gh * N_NODES * NHID;
    const float* f2g = d_f2 + (size_t)gh * N_NODES;
    const unsigned long long* bits0 = d_abits + ((size_t)g_ * N_NODES + R0) * 48;
    const unsigned long long* bits1 = d_abits + ((size_t)g_ * N_NODES + R1) * 48;
    const float f1a = d_f1[(size_t)gh * N_NODES + R0];
    const float f1b = d_f1[(size_t)gh * N_NODES + R1];

    float acc[8][4];
#pragma unroll
    for (int nt = 0; nt < 8; nt++)
#pragma unroll
        for (int j = 0; j < 4; j++) acc[nt][j] = 0.f;
    float rmax0 = -INFINITY, rmax1 = -INFINITY, rsum0 = 0.f, rsum1 = 0.f;

    for (int m0 = 0; m0 < N_NODES; m0 += 64) {
        const int buf = (m0 >> 6) & 1;
        // stage Wh m-tile (pre-cvt tf32, B-swizzled)
#pragma unroll
        for (int it = 0; it < 8; it++) {
            int idx = t + it * 128;
            int k = idx >> 4, n4 = (idx & 15) * 4;
            float4 v = *(const float4*)(Whg + (size_t)(m0 + k) * NHID + n4);
            int o = bswz(k, n4);
            Whs[buf][o] = f2tf32(v.x); Whs[buf][o + 1] = f2tf32(v.y);
            Whs[buf][o + 2] = f2tf32(v.z); Whs[buf][o + 3] = f2tf32(v.w);
        }
        if (t < 64) f2s[buf][t] = f2g[m0 + t];
        __syncthreads();

        const unsigned long long B0 = bits0[m0 >> 6];
        const unsigned long long B1 = bits1[m0 >> 6];

        // scores directly in A-fragment layout
        float p[8][4];
        float tm0 = -INFINITY, tm1 = -INFINITY;
#pragma unroll
        for (int kt = 0; kt < 8; kt++) {
            int c0 = 8 * kt + q, c1 = c0 + 4;
            float fa = f2s[buf][c0], fb = f2s[buf][c1];
            float s00 = f1a + fa; s00 = s00 > 0.f ? s00 : ALPHA * s00;
            float s10 = f1b + fa; s10 = s10 > 0.f ? s10 : ALPHA * s10;
            float s01 = f1a + fb; s01 = s01 > 0.f ? s01 : ALPHA * s01;
            float s11 = f1b + fb; s11 = s11 > 0.f ? s11 : ALPHA * s11;
            s00 = ((B0 >> c0) & 1ull) ? s00 : NEG_INF_F;
            s10 = ((B1 >> c0) & 1ull) ? s10 : NEG_INF_F;
            s01 = ((B0 >> c1) & 1ull) ? s01 : NEG_INF_F;
            s11 = ((B1 >> c1) & 1ull) ? s11 : NEG_INF_F;
            p[kt][0] = s00; p[kt][1] = s10; p[kt][2] = s01; p[kt][3] = s11;
            tm0 = fmaxf(tm0, fmaxf(s00, s01));
            tm1 = fmaxf(tm1, fmaxf(s10, s11));
        }
        tm0 = fmaxf(tm0, __shfl_xor_sync(0xffffffffu, tm0, 1));
        tm0 = fmaxf(tm0, __shfl_xor_sync(0xffffffffu, tm0, 2));
        tm1 = fmaxf(tm1, __shfl_xor_sync(0xffffffffu, tm1, 1));
        tm1 = fmaxf(tm1, __shfl_xor_sync(0xffffffffu, tm1, 2));

        float nm0 = fmaxf(rmax0, tm0), nm1 = fmaxf(rmax1, tm1);
        float sc0 = __expf(rmax0 - nm0), sc1 = __expf(rmax1 - nm1);
        rmax0 = nm0; rmax1 = nm1;
        float ls0 = 0.f, ls1 = 0.f;
#pragma unroll
        for (int kt = 0; kt < 8; kt++) {
            p[kt][0] = __expf(p[kt][0] - nm0);
            p[kt][1] = __expf(p[kt][1] - nm1);
            p[kt][2] = __expf(p[kt][2] - nm0);
            p[kt][3] = __expf(p[kt][3] - nm1);
            ls0 += p[kt][0] + p[kt][2];
            ls1 += p[kt][1] + p[kt][3];
        }
        ls0 += __shfl_xor_sync(0xffffffffu, ls0, 1);
        ls0 += __shfl_xor_sync(0xffffffffu, ls0, 2);
        ls1 += __shfl_xor_sync(0xffffffffu, ls1, 1);
        ls1 += __shfl_xor_sync(0xffffffffu, ls1, 2);
        rsum0 = rsum0 * sc0 + ls0;
        rsum1 = rsum1 * sc1 + ls1;
#pragma unroll
        for (int nt = 0; nt < 8; nt++) {
            acc[nt][0] *= sc0; acc[nt][1] *= sc0;
            acc[nt][2] *= sc1; acc[nt][3] *= sc1;
        }
        // acc += P @ Wh_tile
#pragma unroll
        for (int kt = 0; kt < 8; kt++) {
            uint32_t a0 = f2tf32(p[kt][0]);
            uint32_t a1 = f2tf32(p[kt][1]);
            uint32_t a2 = f2tf32(p[kt][2]);
            uint32_t a3 = f2tf32(p[kt][3]);
#pragma unroll
            for (int nt = 0; nt < 8; nt++) {
                uint32_t b0 = Whs[buf][bswz(8 * kt + q,     8 * nt + gi)];
                uint32_t b1 = Whs[buf][bswz(8 * kt + q + 4, 8 * nt + gi)];
                mma_tf32(acc[nt], a0, a1, a2, a3, b0, b1);
            }
        }
    }

    // epilogue: normalize, ELU, write [g][n][h*64+o]
    const float inv0 = 1.0f / rsum0, inv1 = 1.0f / rsum1;
    float* outg = d_hcat + (size_t)g_ * N_NODES * DCAT;
#pragma unroll
    for (int nt = 0; nt < 8; nt++) {
        float v0 = acc[nt][0] * inv0, v1 = acc[nt][1] * inv0;
        float v2 = acc[nt][2] * inv1, v3 = acc[nt][3] * inv1;
        v0 = v0 > 0.f ? v0 : (__expf(v0) - 1.f);
        v1 = v1 > 0.f ? v1 : (__expf(v1) - 1.f);
        v2 = v2 > 0.f ? v2 : (__expf(v2) - 1.f);
        v3 = v3 > 0.f ? v3 : (__expf(v3) - 1.f);
        *(float2*)(outg + (size_t)R0 * DCAT + h * NHID + 8 * nt + 2 * q) =
            make_float2(v0, v1);
        *(float2*)(outg + (size_t)R1 * DCAT + h * NHID + 8 * nt + 2 * q) =
            make_float2(v2, v3);
    }
}

// ============================================================
// K3: xi = elu(hcat @ W_int^T + b_int) -> out @ W_fus^T + b_fus -> log_softmax
// one warp per node. grid 768, 128 threads.
// ============================================================
__global__ __launch_bounds__(128) void k3_out(const float* __restrict__ Wint,
                                              const float* __restrict__ bint,
                                              const float* __restrict__ Wfus,
                                              const float* __restrict__ bfus,
                                              float* __restrict__ out) {
    __shared__ float sWi[NCLASS * DCAT];
    __shared__ float sWf[NCLASS * (NCLASS * NGRAPH)];
    __shared__ float sbi[NCLASS], sbf[NCLASS];
    const int t = threadIdx.x;
    for (int i = t; i < NCLASS * DCAT; i += 128) sWi[i] = Wint[i];
    for (int i = t; i < NCLASS * NCLASS * NGRAPH; i += 128) sWf[i] = Wfus[i];
    if (t < NCLASS) { sbi[t] = bint[t]; sbf[t] = bfus[t]; }
    __syncthreads();

    const int w = t >> 5, lane = t & 31;
    const int n = blockIdx.x * 4 + w;

    float r[NGRAPH][8];
#pragma unroll
    for (int g = 0; g < NGRAPH; g++)
#pragma unroll
        for (int k = 0; k < 8; k++)
            r[g][k] = d_hcat[(size_t)g * N_NODES * DCAT + (size_t)n * DCAT + lane + 32 * k];

    float xi[48];
#pragma unroll
    for (int j = 0; j < 48; j++) {
        int g = j >> 4, c = j & 15;
        float s = 0.f;
#pragma unroll
        for (int k = 0; k < 8; k++) s += r[g][k] * sWi[c * DCAT + lane + 32 * k];
#pragma unroll
        for (int off = 16; off > 0; off >>= 1)
            s += __shfl_xor_sync(0xffffffffu, s, off);
        s += sbi[c];
        xi[j] = s > 0.f ? s : (__expf(s) - 1.0f);
    }

    int cc = lane & 15;
    float o = sbf[cc];
#pragma unroll
    for (int j = 0; j < 48; j++) o += xi[j] * sWf[cc * 48 + j];

    float m = o;
#pragma unroll
    for (int off = 1; off < 16; off <<= 1)
        m = fmaxf(m, __shfl_xor_sync(0xffffffffu, m, off));
    float e = __expf(o - m), se = e;
#pragma unroll
    for (int off = 1; off < 16; off <<= 1)
        se += __shfl_xor_sync(0xffffffffu, se, off);
    float lp = o - m - logf(se);
    if (lane < 16) out[(size_t)n * NCLASS + cc] = lp;
}

// ============================================================
// K4: l1 loss = mean |W_fus|
// ============================================================
__global__ void k4_loss(const float* __restrict__ Wfus, float* __restrict__ out) {
    __shared__ float s[256];
    const int t = threadIdx.x;
    float v = 0.f;
    for (int i = t; i < NCLASS * NCLASS * NGRAPH; i += 256) v += fabsf(Wfus[i]);
    s[t] = v;
    __syncthreads();
    for (int st = 128; st > 0; st >>= 1) {
        if (t < st) s[t] += s[t + st];
        __syncthreads();
    }
    if (t == 0) out[N_NODES * NCLASS] = s[0] / (float)(NCLASS * NCLASS * NGRAPH);
}

// ============================================================
extern "C" void kernel_launch(void* const* d_in, const int* in_sizes, int n_in,
                              void* d_out, int out_size) {
    const float* x    = (const float*)d_in[0];
    const int*   adj  = (const int*)  d_in[1];
    const float* W    = (const float*)d_in[2];
    const float* a    = (const float*)d_in[3];
    const float* Wint = (const float*)d_in[4];
    const float* bint = (const float*)d_in[5];
    const float* Wfus = (const float*)d_in[6];
    const float* bfus = (const float*)d_in[7];
    float* out = (float*)d_out;

    k0_pack<<<NGRAPH * N_NODES / 8, 256>>>(adj);
    k1_wh<<<dim3(N_NODES / 64, NGH), 128>>>(x, W);
    k1_f<<<NGH * N_NODES / 8, 256>>>(a);
    k2_attn<<<dim3(N_NODES / 64, NHEADS, NGRAPH), 128>>>();
    k3_out<<<N_NODES / 4, 128>>>(Wint, bint, Wfus, bfus, out);
    if (out_size > N_NODES * NCLASS)
        k4_loss<<<1, 256>>>(Wfus, out);
}

// round 8
// speedup vs baseline: 4.7186x; 1.2533x over previous
#include <cuda_runtime.h>
#include <math.h>
#include <stdint.h>

#define N_NODES 3072
#define F_IN 512
#define NHID 64
#define NHEADS 4
#define NGRAPH 3
#define NCLASS 16
#define NGH (NGRAPH * NHEADS)
#define DCAT (NHEADS * NHID)   // 256
#define ALPHA 0.2f
#define NEG_INF_F (-9000000000000000.0f)

// -------- scratch (no allocations allowed) --------
__device__ float d_Wh[NGH * N_NODES * NHID];                 // [gh][n][o] fp32
__device__ float d_f1[NGH * N_NODES];
__device__ float d_f2[NGH * N_NODES];
__device__ float d_hcat[NGRAPH * N_NODES * DCAT];            // [g][n][h*64+o]
__device__ unsigned long long d_abits[NGRAPH * N_NODES * 48]; // bitpacked adj

// ---------- helpers ----------
__device__ __forceinline__ uint32_t f2tf32(float f) {
    uint32_t u;
    asm("cvt.rna.tf32.f32 %0, %1;" : "=r"(u) : "f"(f));
    return u;
}
__device__ __forceinline__ uint32_t pkbf2(float lo, float hi) {
    uint32_t r;
    asm("cvt.rn.bf16x2.f32 %0, %1, %2;" : "=r"(r) : "f"(hi), "f"(lo));
    return r;
}
__device__ __forceinline__ void mma_tf32(float d[4], uint32_t a0, uint32_t a1,
                                         uint32_t a2, uint32_t a3,
                                         uint32_t b0, uint32_t b1) {
    asm volatile(
        "mma.sync.aligned.m16n8k8.row.col.f32.tf32.tf32.f32 "
        "{%0,%1,%2,%3},{%4,%5,%6,%7},{%8,%9},{%0,%1,%2,%3};\n"
        : "+f"(d[0]), "+f"(d[1]), "+f"(d[2]), "+f"(d[3])
        : "r"(a0), "r"(a1), "r"(a2), "r"(a3), "r"(b0), "r"(b1));
}
__device__ __forceinline__ void mma_bf16(float d[4], uint32_t a0, uint32_t a1,
                                         uint32_t a2, uint32_t a3,
                                         uint32_t b0, uint32_t b1) {
    asm volatile(
        "mma.sync.aligned.m16n8k16.row.col.f32.bf16.bf16.f32 "
        "{%0,%1,%2,%3},{%4,%5,%6,%7},{%8,%9},{%0,%1,%2,%3};\n"
        : "+f"(d[0]), "+f"(d[1]), "+f"(d[2]), "+f"(d[3])
        : "r"(a0), "r"(a1), "r"(a2), "r"(a3), "r"(b0), "r"(b1));
}
// word-granular swizzle: word (kp, n) of [32or64]x64 word tile.
// reads at kp = 8kt+q (+4), n = 8nt+gi -> bank = gi + 8*((nt^q)&3): 32 distinct.
__device__ __forceinline__ int bswz(int k, int n) {
    return k * 64 + (n ^ ((k & 3) << 3));
}
// A-operand swizzle for k1 (tf32): reads (r=16w+gi[+8], c=8kt+q[+4]) conflict-free.
__device__ __forceinline__ int aswz(int r, int c) {
    return r * 64 + (c ^ ((r & 3) << 3) ^ (r & 4));
}

// ============================================================
// K0: bitpack adj (int32 0/1 -> 64-bit masks). One warp per row.
// ============================================================
__global__ __launch_bounds__(256) void k0_pack(const int* __restrict__ adj) {
    const int row = blockIdx.x * 8 + (threadIdx.x >> 5);  // g*N + n
    const int lane = threadIdx.x & 31;
    const int* arow = adj + (size_t)row * N_NODES;
    unsigned long long* brow = d_abits + (size_t)row * 48;
    for (int j = 0; j < 48; j++) {
        unsigned lo = __ballot_sync(0xffffffffu, arow[j * 64 + lane] != 0);
        unsigned hi = __ballot_sync(0xffffffffu, arow[j * 64 + 32 + lane] != 0);
        if (lane == 0) brow[j] = ((unsigned long long)hi << 32) | lo;
    }
}

// ============================================================
// K1: Wh[gh] = x @ W[gh] via tf32 mma. grid (48,12), 128 thr.
// (fp32 output kept for the f1/f2 score path)
// ============================================================
__global__ __launch_bounds__(128) void k1_wh(const float* __restrict__ x,
                                             const float* __restrict__ W) {
    __shared__ uint32_t As[64 * 64];
    __shared__ uint32_t Bs[64 * 64];
    const int gh = blockIdx.y, n0 = blockIdx.x * 64;
    const int t = threadIdx.x, lane = t & 31, w = t >> 5;
    const int gi = lane >> 2, q = lane & 3;
    const float* Wg = W + (size_t)gh * F_IN * NHID;

    float acc[8][4];
#pragma unroll
    for (int nt = 0; nt < 8; nt++)
#pragma unroll
        for (int j = 0; j < 4; j++) acc[nt][j] = 0.f;

    for (int k0 = 0; k0 < F_IN; k0 += 64) {
        __syncthreads();
#pragma unroll
        for (int it = 0; it < 8; it++) {
            int idx = t + it * 128;
            int r = idx >> 4, c4 = (idx & 15) * 4;
            float4 v = *(const float4*)(x + (size_t)(n0 + r) * F_IN + k0 + c4);
            int o = aswz(r, c4);
            As[o] = f2tf32(v.x); As[o + 1] = f2tf32(v.y);
            As[o + 2] = f2tf32(v.z); As[o + 3] = f2tf32(v.w);
        }
#pragma unroll
        for (int it = 0; it < 8; it++) {
            int idx = t + it * 128;
            int k = idx >> 4, n4 = (idx & 15) * 4;
            float4 v = *(const float4*)(Wg + (size_t)(k0 + k) * NHID + n4);
            int o = bswz(k, n4);
            Bs[o] = f2tf32(v.x); Bs[o + 1] = f2tf32(v.y);
            Bs[o + 2] = f2tf32(v.z); Bs[o + 3] = f2tf32(v.w);
        }
        __syncthreads();
#pragma unroll
        for (int kt = 0; kt < 8; kt++) {
            uint32_t a0 = As[aswz(16 * w + gi,     8 * kt + q)];
            uint32_t a1 = As[aswz(16 * w + gi + 8, 8 * kt + q)];
            uint32_t a2 = As[aswz(16 * w + gi,     8 * kt + q + 4)];
            uint32_t a3 = As[aswz(16 * w + gi + 8, 8 * kt + q + 4)];
#pragma unroll
            for (int nt = 0; nt < 8; nt++) {
                uint32_t b0 = Bs[bswz(8 * kt + q,     8 * nt + gi)];
                uint32_t b1 = Bs[bswz(8 * kt + q + 4, 8 * nt + gi)];
                mma_tf32(acc[nt], a0, a1, a2, a3, b0, b1);
            }
        }
    }
    float* out = d_Wh + (size_t)gh * N_NODES * NHID;
    const int R0 = n0 + 16 * w + gi, R1 = R0 + 8;
#pragma unroll
    for (int nt = 0; nt < 8; nt++) {
        *(float2*)(out + (size_t)R0 * NHID + 8 * nt + 2 * q) =
            make_float2(acc[nt][0], acc[nt][1]);
        *(float2*)(out + (size_t)R1 * NHID + 8 * nt + 2 * q) =
            make_float2(acc[nt][2], acc[nt][3]);
    }
}

// ============================================================
// K1b: f1/f2 = Wh . a1 / a2   (one warp per (gh,n) row)
// ============================================================
__global__ __launch_bounds__(256) void k1_f(const float* __restrict__ a) {
    const int w = threadIdx.x >> 5, lane = threadIdx.x & 31;
    const int row = blockIdx.x * 8 + w;
    const int gh = row / N_NODES;
    const float* whrow = d_Wh + (size_t)row * NHID;
    const float* ag = a + (size_t)gh * 2 * NHID;
    float w0 = whrow[lane], w1 = whrow[lane + 32];
    float s1 = w0 * ag[lane] + w1 * ag[lane + 32];
    float s2 = w0 * ag[64 + lane] + w1 * ag[96 + lane];
#pragma unroll
    for (int off = 16; off > 0; off >>= 1) {
        s1 += __shfl_xor_sync(0xffffffffu, s1, off);
        s2 += __shfl_xor_sync(0xffffffffu, s2, off);
    }
    if (lane == 0) { d_f1[row] = s1; d_f2[row] = s2; }
}

// ============================================================
// K2: fused attention, NO online max (scores bounded |e| < ~6),
// P@Wh on bf16 m16n8k16 tensor cores. grid (48, NHEADS, NGRAPH), 128 thr.
// ============================================================
__global__ __launch_bounds__(128) void k2_attn() {
    __shared__ uint32_t Whs[2][32 * 64];   // bf16x2 words: {lo=Wh[2kp][n], hi=Wh[2kp+1][n]}
    __shared__ float f2s[2][64];
    const int g_ = blockIdx.z, h = blockIdx.y;
    const int gh = g_ * NHEADS + h;
    const int n0 = blockIdx.x * 64;
    const int t = threadIdx.x, lane = t & 31, w = t >> 5;
    const int gi = lane >> 2, q = lane & 3;
    const int qx = q << 3;
    const int R0 = n0 + 16 * w + gi, R1 = R0 + 8;

    const float* Whg = d_Wh + (size_t)gh * N_NODES * NHID;
    const float* f2g = d_f2 + (size_t)gh * N_NODES;
    const unsigned long long* bits0 = d_abits + ((size_t)g_ * N_NODES + R0) * 48;
    const unsigned long long* bits1 = d_abits + ((size_t)g_ * N_NODES + R1) * 48;
    const float f1a = d_f1[(size_t)gh * N_NODES + R0];
    const float f1b = d_f1[(size_t)gh * N_NODES + R1];

    // precomputed swizzled column index per nt
    int nxs[8];
#pragma unroll
    for (int nt = 0; nt < 8; nt++) nxs[nt] = (8 * nt + gi) ^ qx;

    float acc[8][4];
#pragma unroll
    for (int nt = 0; nt < 8; nt++)
#pragma unroll
        for (int j = 0; j < 4; j++) acc[nt][j] = 0.f;
    float rs0 = 0.f, rs1 = 0.f;   // per-lane partial sums of p

    for (int m0 = 0; m0 < N_NODES; m0 += 64) {
        const int buf = (m0 >> 6) & 1;
        // stage Wh m-tile: pack k-adjacent row pairs into bf16x2, swizzled
#pragma unroll
        for (int it = 0; it < 4; it++) {
            int idx = t + it * 128;          // 0..511
            int kp = idx >> 4, n4 = (idx & 15) * 4;
            const float* src = Whg + (size_t)(m0 + 2 * kp) * NHID + n4;
            float4 r0 = *(const float4*)(src);
            float4 r1 = *(const float4*)(src + NHID);
            uint4 wd;
            wd.x = pkbf2(r0.x, r1.x); wd.y = pkbf2(r0.y, r1.y);
            wd.z = pkbf2(r0.z, r1.z); wd.w = pkbf2(r0.w, r1.w);
            *(uint4*)&Whs[buf][bswz(kp, n4)] = wd;
        }
        if (t < 64) f2s[buf][t] = f2g[m0 + t];
        __syncthreads();

        const unsigned long long B0 = bits0[m0 >> 6];
        const unsigned long long B1 = bits1[m0 >> 6];

#pragma unroll
        for (int kt = 0; kt < 4; kt++) {
            const int cb = 16 * kt + 2 * q;
            const float fa0 = f2s[buf][cb],     fa1 = f2s[buf][cb + 1];
            const float fb0 = f2s[buf][cb + 8], fb1 = f2s[buf][cb + 9];
            const uint32_t m0b = (uint32_t)(B0 >> cb);
            const uint32_t m1b = (uint32_t)(B1 >> cb);

            float s;
            s = f1a + fa0; s = s > 0.f ? s : ALPHA * s; float p00 = __expf(s);
            s = f1a + fa1; s = s > 0.f ? s : ALPHA * s; float p01 = __expf(s);
            s = f1a + fb0; s = s > 0.f ? s : ALPHA * s; float p02 = __expf(s);
            s = f1a + fb1; s = s > 0.f ? s : ALPHA * s; float p03 = __expf(s);
            s = f1b + fa0; s = s > 0.f ? s : ALPHA * s; float p10 = __expf(s);
            s = f1b + fa1; s = s > 0.f ? s : ALPHA * s; float p11 = __expf(s);
            s = f1b + fb0; s = s > 0.f ? s : ALPHA * s; float p12 = __expf(s);
            s = f1b + fb1; s = s > 0.f ? s : ALPHA * s; float p13 = __expf(s);

            p00 = (m0b & 1u)      ? p00 : 0.f;
            p01 = (m0b & 2u)      ? p01 : 0.f;
            p02 = (m0b & 0x100u)  ? p02 : 0.f;
            p03 = (m0b & 0x200u)  ? p03 : 0.f;
            p10 = (m1b & 1u)      ? p10 : 0.f;
            p11 = (m1b & 2u)      ? p11 : 0.f;
            p12 = (m1b & 0x100u)  ? p12 : 0.f;
            p13 = (m1b & 0x200u)  ? p13 : 0.f;

            rs0 += (p00 + p01) + (p02 + p03);
            rs1 += (p10 + p11) + (p12 + p13);

            const uint32_t a0 = pkbf2(p00, p01);
            const uint32_t a1 = pkbf2(p10, p11);
            const uint32_t a2 = pkbf2(p02, p03);
            const uint32_t a3 = pkbf2(p12, p13);
            const int kb0 = (8 * kt + q) * 64;
            const int kb1 = kb0 + 4 * 64;
#pragma unroll
            for (int nt = 0; nt < 8; nt++) {
                uint32_t b0 = Whs[buf][kb0 + nxs[nt]];
                uint32_t b1 = Whs[buf][kb1 + nxs[nt]];
                mma_bf16(acc[nt], a0, a1, a2, a3, b0, b1);
            }
        }
    }

    // single lane reduction at the end (cols owned per q cover all 64 after xor 1,2)
    rs0 += __shfl_xor_sync(0xffffffffu, rs0, 1);
    rs0 += __shfl_xor_sync(0xffffffffu, rs0, 2);
    rs1 += __shfl_xor_sync(0xffffffffu, rs1, 1);
    rs1 += __shfl_xor_sync(0xffffffffu, rs1, 2);

    const float inv0 = 1.0f / rs0, inv1 = 1.0f / rs1;
    float* outg = d_hcat + (size_t)g_ * N_NODES * DCAT;
#pragma unroll
    for (int nt = 0; nt < 8; nt++) {
        float v0 = acc[nt][0] * inv0, v1 = acc[nt][1] * inv0;
        float v2 = acc[nt][2] * inv1, v3 = acc[nt][3] * inv1;
        v0 = v0 > 0.f ? v0 : (__expf(v0) - 1.f);
        v1 = v1 > 0.f ? v1 : (__expf(v1) - 1.f);
        v2 = v2 > 0.f ? v2 : (__expf(v2) - 1.f);
        v3 = v3 > 0.f ? v3 : (__expf(v3) - 1.f);
        *(float2*)(outg + (size_t)R0 * DCAT + h * NHID + 8 * nt + 2 * q) =
            make_float2(v0, v1);
        *(float2*)(outg + (size_t)R1 * DCAT + h * NHID + 8 * nt + 2 * q) =
            make_float2(v2, v3);
    }
}

// ============================================================
// K3: xi = elu(hcat @ W_int^T + b_int) -> @ W_fus^T + b_fus -> log_softmax
// thread = (node, class). grid 192 x 256 thr (16 nodes/block).
// ============================================================
__global__ __launch_bounds__(256) void k3_out(const float* __restrict__ Wint,
                                              const float* __restrict__ bint,
                                              const float* __restrict__ Wfus,
                                              const float* __restrict__ bfus,
                                              float* __restrict__ out) {
    __shared__ float sWt[DCAT * 17];                 // W_int transposed, pad 17
    __shared__ float sWf[NCLASS * 49];               // W_fus, pad 49
    __shared__ float sXi[16 * 48];
    __shared__ float sbi[NCLASS], sbf[NCLASS];
    const int t = threadIdx.x;
    for (int i = t; i < NCLASS * DCAT; i += 256) {
        int c = i >> 8, k = i & 255;
        sWt[k * 17 + c] = Wint[i];
    }
    for (int i = t; i < NCLASS * 48; i += 256) {
        int c = i / 48, j = i - c * 48;
        sWf[c * 49 + j] = Wfus[i];
    }
    if (t < NCLASS) { sbi[t] = bint[t]; sbf[t] = bfus[t]; }
    __syncthreads();

    const int nb = t >> 4, c = t & 15;
    const int n = blockIdx.x * 16 + nb;

#pragma unroll
    for (int g = 0; g < NGRAPH; g++) {
        const float* hp = d_hcat + ((size_t)g * N_NODES + n) * DCAT;
        float acc = 0.f;
#pragma unroll 8
        for (int k0 = 0; k0 < DCAT; k0 += 4) {
            float4 h4 = *(const float4*)(hp + k0);
            acc += h4.x * sWt[(k0 + 0) * 17 + c];
            acc += h4.y * sWt[(k0 + 1) * 17 + c];
            acc += h4.z * sWt[(k0 + 2) * 17 + c];
            acc += h4.w * sWt[(k0 + 3) * 17 + c];
        }
        float xv = acc + sbi[c];
        sXi[nb * 48 + g * 16 + c] = xv > 0.f ? xv : (__expf(xv) - 1.f);
    }
    __syncthreads();

    float o = sbf[c];
#pragma unroll
    for (int j = 0; j < 48; j++) o += sXi[nb * 48 + j] * sWf[c * 49 + j];

    float m = o;
#pragma unroll
    for (int off = 1; off < 16; off <<= 1)
        m = fmaxf(m, __shfl_xor_sync(0xffffffffu, m, off));
    float e = __expf(o - m), se = e;
#pragma unroll
    for (int off = 1; off < 16; off <<= 1)
        se += __shfl_xor_sync(0xffffffffu, se, off);
    out[(size_t)n * NCLASS + c] = o - m - __logf(se);
}

// ============================================================
// K4: l1 loss = mean |W_fus|
// ============================================================
__global__ void k4_loss(const float* __restrict__ Wfus, float* __restrict__ out) {
    __shared__ float s[256];
    const int t = threadIdx.x;
    float v = 0.f;
    for (int i = t; i < NCLASS * NCLASS * NGRAPH; i += 256) v += fabsf(Wfus[i]);
    s[t] = v;
    __syncthreads();
    for (int st = 128; st > 0; st >>= 1) {
        if (t < st) s[t] += s[t + st];
        __syncthreads();
    }
    if (t == 0) out[N_NODES * NCLASS] = s[0] / (float)(NCLASS * NCLASS * NGRAPH);
}

// ============================================================
extern "C" void kernel_launch(void* const* d_in, const int* in_sizes, int n_in,
                              void* d_out, int out_size) {
    const float* x    = (const float*)d_in[0];
    const int*   adj  = (const int*)  d_in[1];
    const float* W    = (const float*)d_in[2];
    const float* a    = (const float*)d_in[3];
    const float* Wint = (const float*)d_in[4];
    const float* bint = (const float*)d_in[5];
    const float* Wfus = (const float*)d_in[6];
    const float* bfus = (const float*)d_in[7];
    float* out = (float*)d_out;

    k0_pack<<<NGRAPH * N_NODES / 8, 256>>>(adj);
    k1_wh<<<dim3(N_NODES / 64, NGH), 128>>>(x, W);
    k1_f<<<NGH * N_NODES / 8, 256>>>(a);
    k2_attn<<<dim3(N_NODES / 64, NHEADS, NGRAPH), 128>>>();
    k3_out<<<N_NODES / 16, 256>>>(Wint, bint, Wfus, bfus, out);
    if (out_size > N_NODES * NCLASS)
        k4_loss<<<1, 256>>>(Wfus, out);
}

// round 10
// speedup vs baseline: 5.5682x; 1.1801x over previous
#include <cuda_runtime.h>
#include <math.h>
#include <stdint.h>

#define N_NODES 3072
#define F_IN 512
#define NHID 64
#define NHEADS 4
#define NGRAPH 3
#define NCLASS 16
#define NGH (NGRAPH * NHEADS)
#define DCAT (NHEADS * NHID)   // 256
#define ALPHA 0.2f

// -------- scratch (no allocations allowed) --------
__device__ uint32_t d_Whbf[NGH * 48 * 2048];                 // bf16x2, tile-swizzled
__device__ float2 d_ef1[NGH * N_NODES];                      // (e^f1, e^{0.2 f1})
__device__ float2 d_ef2[NGH * N_NODES];                      // (e^f2, e^{0.2 f2})
__device__ float d_hcat[NGRAPH * N_NODES * DCAT];            // [g][n][h*64+o]
__device__ unsigned long long d_abits[NGRAPH * N_NODES * 48]; // bitpacked adj

// ---------- helpers ----------
__device__ __forceinline__ uint32_t f2tf32(float f) {
    uint32_t u;
    asm("cvt.rna.tf32.f32 %0, %1;" : "=r"(u) : "f"(f));
    return u;
}
__device__ __forceinline__ uint32_t pkbf2(float lo, float hi) {
    uint32_t r;
    asm("cvt.rn.bf16x2.f32 %0, %1, %2;" : "=r"(r) : "f"(hi), "f"(lo));
    return r;
}
__device__ __forceinline__ void mma_tf32(float d[4], uint32_t a0, uint32_t a1,
                                         uint32_t a2, uint32_t a3,
                                         uint32_t b0, uint32_t b1) {
    asm volatile(
        "mma.sync.aligned.m16n8k8.row.col.f32.tf32.tf32.f32 "
        "{%0,%1,%2,%3},{%4,%5,%6,%7},{%8,%9},{%0,%1,%2,%3};\n"
        : "+f"(d[0]), "+f"(d[1]), "+f"(d[2]), "+f"(d[3])
        : "r"(a0), "r"(a1), "r"(a2), "r"(a3), "r"(b0), "r"(b1));
}
__device__ __forceinline__ void mma_bf16(float d[4], uint32_t a0, uint32_t a1,
                                         uint32_t a2, uint32_t a3,
                                         uint32_t b0, uint32_t b1) {
    asm volatile(
        "mma.sync.aligned.m16n8k16.row.col.f32.bf16.bf16.f32 "
        "{%0,%1,%2,%3},{%4,%5,%6,%7},{%8,%9},{%0,%1,%2,%3};\n"
        : "+f"(d[0]), "+f"(d[1]), "+f"(d[2]), "+f"(d[3])
        : "r"(a0), "r"(a1), "r"(a2), "r"(a3), "r"(b0), "r"(b1));
}
// word-granular swizzle: word (kp, n) of a [32|64]x64 word tile.
__device__ __forceinline__ int bswz(int k, int n) {
    return k * 64 + (n ^ ((k & 3) << 3));
}
__device__ __forceinline__ int aswz(int r, int c) {
    return r * 64 + (c ^ ((r & 3) << 3) ^ (r & 4));
}
// cp.async
__device__ __forceinline__ void cpa16(void* smem_dst, const void* gsrc) {
    uint32_t d = (uint32_t)__cvta_generic_to_shared(smem_dst);
    asm volatile("cp.async.ca.shared.global [%0], [%1], 16;\n" :: "r"(d), "l"(gsrc));
}
__device__ __forceinline__ void cpa_commit() {
    asm volatile("cp.async.commit_group;\n");
}
template <int NW> __device__ __forceinline__ void cpa_wait() {
    asm volatile("cp.async.wait_group %0;\n" :: "n"(NW));
}

// ============================================================
// K0: bitpack adj (int32 0/1 -> 64-bit masks). One warp per row.
// ============================================================
__global__ __launch_bounds__(256) void k0_pack(const int* __restrict__ adj) {
    const int row = blockIdx.x * 8 + (threadIdx.x >> 5);  // g*N + n
    const int lane = threadIdx.x & 31;
    const int* arow = adj + (size_t)row * N_NODES;
    unsigned long long* brow = d_abits + (size_t)row * 48;
    for (int j = 0; j < 48; j++) {
        unsigned lo = __ballot_sync(0xffffffffu, arow[j * 64 + lane] != 0);
        unsigned hi = __ballot_sync(0xffffffffu, arow[j * 64 + 32 + lane] != 0);
        if (lane == 0) brow[j] = ((unsigned long long)hi << 32) | lo;
    }
}

// ============================================================
// K1: Wh = x @ W via tf32 mma; epilogue fuses:
//   - f1/f2 row factors -> exp forms (d_ef1/d_ef2)
//   - bf16 pack + tile swizzle -> d_Whbf (k2-ready)
// grid (48, 12), 128 thr.
// ============================================================
__global__ __launch_bounds__(128) void k1_wh(const float* __restrict__ x,
                                             const float* __restrict__ W,
                                             const float* __restrict__ a) {
    __shared__ uint32_t As[64 * 64];
    __shared__ uint32_t Bs[64 * 64];
    __shared__ float sa[128];
    const int gh = blockIdx.y, n0 = blockIdx.x * 64;
    const int t = threadIdx.x, lane = t & 31, w = t >> 5;
    const int gi = lane >> 2, q = lane & 3;
    const float* Wg = W + (size_t)gh * F_IN * NHID;
    if (t < 128) sa[t] = a[gh * 128 + t];

    float acc[8][4];
#pragma unroll
    for (int nt = 0; nt < 8; nt++)
#pragma unroll
        for (int j = 0; j < 4; j++) acc[nt][j] = 0.f;

    for (int k0 = 0; k0 < F_IN; k0 += 64) {
        __syncthreads();
#pragma unroll
        for (int it = 0; it < 8; it++) {
            int idx = t + it * 128;
            int r = idx >> 4, c4 = (idx & 15) * 4;
            float4 v = *(const float4*)(x + (size_t)(n0 + r) * F_IN + k0 + c4);
            int o = aswz(r, c4);
            As[o] = f2tf32(v.x); As[o + 1] = f2tf32(v.y);
            As[o + 2] = f2tf32(v.z); As[o + 3] = f2tf32(v.w);
        }
#pragma unroll
        for (int it = 0; it < 8; it++) {
            int idx = t + it * 128;
            int k = idx >> 4, n4 = (idx & 15) * 4;
            float4 v = *(const float4*)(Wg + (size_t)(k0 + k) * NHID + n4);
            int o = bswz(k, n4);
            Bs[o] = f2tf32(v.x); Bs[o + 1] = f2tf32(v.y);
            Bs[o + 2] = f2tf32(v.z); Bs[o + 3] = f2tf32(v.w);
        }
        __syncthreads();
#pragma unroll
        for (int kt = 0; kt < 8; kt++) {
            uint32_t a0 = As[aswz(16 * w + gi,     8 * kt + q)];
            uint32_t a1 = As[aswz(16 * w + gi + 8, 8 * kt + q)];
            uint32_t a2 = As[aswz(16 * w + gi,     8 * kt + q + 4)];
            uint32_t a3 = As[aswz(16 * w + gi + 8, 8 * kt + q + 4)];
#pragma unroll
            for (int nt = 0; nt < 8; nt++) {
                uint32_t b0 = Bs[bswz(8 * kt + q,     8 * nt + gi)];
                uint32_t b1 = Bs[bswz(8 * kt + q + 4, 8 * nt + gi)];
                mma_tf32(acc[nt], a0, a1, a2, a3, b0, b1);
            }
        }
    }

    const int R0 = n0 + 16 * w + gi, R1 = R0 + 8;

    // ---- f1/f2 (full-precision fragments), then exp forms ----
    float p10 = 0.f, p20 = 0.f, p11 = 0.f, p21 = 0.f;
#pragma unroll
    for (int nt = 0; nt < 8; nt++) {
        int c0 = 8 * nt + 2 * q;
        p10 += acc[nt][0] * sa[c0]      + acc[nt][1] * sa[c0 + 1];
        p20 += acc[nt][0] * sa[64 + c0] + acc[nt][1] * sa[64 + c0 + 1];
        p11 += acc[nt][2] * sa[c0]      + acc[nt][3] * sa[c0 + 1];
        p21 += acc[nt][2] * sa[64 + c0] + acc[nt][3] * sa[64 + c0 + 1];
    }
#pragma unroll
    for (int off = 1; off < 4; off <<= 1) {
        p10 += __shfl_xor_sync(0xffffffffu, p10, off);
        p20 += __shfl_xor_sync(0xffffffffu, p20, off);
        p11 += __shfl_xor_sync(0xffffffffu, p11, off);
        p21 += __shfl_xor_sync(0xffffffffu, p21, off);
    }
    if (q == 0) {
        d_ef1[(size_t)gh * N_NODES + R0] = make_float2(__expf(p10), __expf(ALPHA * p10));
        d_ef2[(size_t)gh * N_NODES + R0] = make_float2(__expf(p20), __expf(ALPHA * p20));
        d_ef1[(size_t)gh * N_NODES + R1] = make_float2(__expf(p11), __expf(ALPHA * p11));
        d_ef2[(size_t)gh * N_NODES + R1] = make_float2(__expf(p21), __expf(ALPHA * p21));
    }

    // ---- bf16 pack, adjacent-row pairing via shfl, swizzled store ----
    uint32_t* dst = d_Whbf + ((size_t)gh * 48 + blockIdx.x) * 2048;
    const bool even = (gi & 1) == 0;
    const int kp = 8 * w + (gi >> 1) + (even ? 0 : 4);
#pragma unroll
    for (int nt = 0; nt < 8; nt++) {
        float o0 = __shfl_xor_sync(0xffffffffu, acc[nt][0], 4);
        float o1 = __shfl_xor_sync(0xffffffffu, acc[nt][1], 4);
        float o2 = __shfl_xor_sync(0xffffffffu, acc[nt][2], 4);
        float o3 = __shfl_xor_sync(0xffffffffu, acc[nt][3], 4);
        uint32_t w0, w1;
        if (even) { w0 = pkbf2(acc[nt][0], o0); w1 = pkbf2(acc[nt][1], o1); }
        else      { w0 = pkbf2(o2, acc[nt][2]); w1 = pkbf2(o3, acc[nt][3]); }
        int c = 8 * nt + 2 * q;
        int o = bswz(kp, c);
        *(uint2*)&dst[o] = make_uint2(w0, w1);
    }
}

// ============================================================
// K2: fused attention. exp(leaky(s)) = max(ea*eb, fa*fb) -- zero MUFU
// in the hot loop. cp.async double-buffered staging of pre-packed bf16 Wh.
// grid (48, NHEADS, NGRAPH), 128 thr.
// ============================================================
__global__ __launch_bounds__(128) void k2_attn() {
    __shared__ uint32_t Whs[2][2048];
    __shared__ float2 efs[2][64];
    const int g_ = blockIdx.z, h = blockIdx.y;
    const int gh = g_ * NHEADS + h;
    const int n0 = blockIdx.x * 64;
    const int t = threadIdx.x, lane = t & 31, w = t >> 5;
    const int gi = lane >> 2, q = lane & 3;
    const int qx = q << 3;
    const int R0 = n0 + 16 * w + gi, R1 = R0 + 8;

    const uint32_t* Wsrc = d_Whbf + (size_t)gh * 48 * 2048;
    const float2* ef2g = d_ef2 + (size_t)gh * N_NODES;
    const unsigned long long* bits0 = d_abits + ((size_t)g_ * N_NODES + R0) * 48;
    const unsigned long long* bits1 = d_abits + ((size_t)g_ * N_NODES + R1) * 48;
    const float2 ef1a = d_ef1[(size_t)gh * N_NODES + R0];
    const float2 ef1b = d_ef1[(size_t)gh * N_NODES + R1];
    const float ea0 = ef1a.x, fa0 = ef1a.y, ea1 = ef1b.x, fa1 = ef1b.y;

    int nxs[8];
#pragma unroll
    for (int nt = 0; nt < 8; nt++) nxs[nt] = (8 * nt + gi) ^ qx;

    float acc[8][4];
#pragma unroll
    for (int nt = 0; nt < 8; nt++)
#pragma unroll
        for (int j = 0; j < 4; j++) acc[nt][j] = 0.f;
    float rs0 = 0.f, rs1 = 0.f;

    // stage tile 0
    {
        const uint32_t* src = Wsrc;
#pragma unroll
        for (int it = 0; it < 4; it++)
            cpa16(&Whs[0][(t + it * 128) * 4], src + (t + it * 128) * 4);
        if (t < 32) cpa16(&efs[0][t * 2], ef2g + t * 2);
        cpa_commit();
    }

    for (int mt = 0; mt < 48; mt++) {
        const int buf = mt & 1;
        if (mt + 1 < 48) {
            const uint32_t* src = Wsrc + (size_t)(mt + 1) * 2048;
#pragma unroll
            for (int it = 0; it < 4; it++)
                cpa16(&Whs[buf ^ 1][(t + it * 128) * 4], src + (t + it * 128) * 4);
            if (t < 32) cpa16(&efs[buf ^ 1][t * 2], ef2g + (mt + 1) * 64 + t * 2);
            cpa_commit();
            cpa_wait<1>();
        } else {
            cpa_wait<0>();
        }
        __syncthreads();

        const uint32_t m0lo = (uint32_t)bits0[mt], m0hi = (uint32_t)(bits0[mt] >> 32);
        const uint32_t m1lo = (uint32_t)bits1[mt], m1hi = (uint32_t)(bits1[mt] >> 32);

#pragma unroll
        for (int kt = 0; kt < 4; kt++) {
            const int cb = 16 * kt + 2 * q;
            const float2 e0 = efs[buf][cb],     e1 = efs[buf][cb + 1];
            const float2 e8 = efs[buf][cb + 8], e9 = efs[buf][cb + 9];
            const uint32_t m0b = (kt < 2) ? (m0lo >> cb) : (m0hi >> (cb - 32));
            const uint32_t m1b = (kt < 2) ? (m1lo >> cb) : (m1hi >> (cb - 32));

            float p00 = fmaxf(ea0 * e0.x, fa0 * e0.y);
            float p01 = fmaxf(ea0 * e1.x, fa0 * e1.y);
            float p02 = fmaxf(ea0 * e8.x, fa0 * e8.y);
            float p03 = fmaxf(ea0 * e9.x, fa0 * e9.y);
            float p10 = fmaxf(ea1 * e0.x, fa1 * e0.y);
            float p11 = fmaxf(ea1 * e1.x, fa1 * e1.y);
            float p12 = fmaxf(ea1 * e8.x, fa1 * e8.y);
            float p13 = fmaxf(ea1 * e9.x, fa1 * e9.y);

            p00 = (m0b & 1u)     ? p00 : 0.f;
            p01 = (m0b & 2u)     ? p01 : 0.f;
            p02 = (m0b & 0x100u) ? p02 : 0.f;
            p03 = (m0b & 0x200u) ? p03 : 0.f;
            p10 = (m1b & 1u)     ? p10 : 0.f;
            p11 = (m1b & 2u)     ? p11 : 0.f;
            p12 = (m1b & 0x100u) ? p12 : 0.f;
            p13 = (m1b & 0x200u) ? p13 : 0.f;

            rs0 += (p00 + p01) + (p02 + p03);
            rs1 += (p10 + p11) + (p12 + p13);

            const uint32_t a0 = pkbf2(p00, p01);
            const uint32_t a1 = pkbf2(p10, p11);
            const uint32_t a2 = pkbf2(p02, p03);
            const uint32_t a3 = pkbf2(p12, p13);
            const int kb0 = (8 * kt + q) * 64;
            const int kb1 = kb0 + 256;
#pragma unroll
            for (int nt = 0; nt < 8; nt++) {
                uint32_t b0 = Whs[buf][kb0 + nxs[nt]];
                uint32_t b1 = Whs[buf][kb1 + nxs[nt]];
                mma_bf16(acc[nt], a0, a1, a2, a3, b0, b1);
            }
        }
        __syncthreads();
    }

    rs0 += __shfl_xor_sync(0xffffffffu, rs0, 1);
    rs0 += __shfl_xor_sync(0xffffffffu, rs0, 2);
    rs1 += __shfl_xor_sync(0xffffffffu, rs1, 1);
    rs1 += __shfl_xor_sync(0xffffffffu, rs1, 2);

    const float inv0 = 1.0f / rs0, inv1 = 1.0f / rs1;
    float* outg = d_hcat + (size_t)g_ * N_NODES * DCAT;
#pragma unroll
    for (int nt = 0; nt < 8; nt++) {
        float v0 = acc[nt][0] * inv0, v1 = acc[nt][1] * inv0;
        float v2 = acc[nt][2] * inv1, v3 = acc[nt][3] * inv1;
        v0 = v0 > 0.f ? v0 : (__expf(v0) - 1.f);
        v1 = v1 > 0.f ? v1 : (__expf(v1) - 1.f);
        v2 = v2 > 0.f ? v2 : (__expf(v2) - 1.f);
        v3 = v3 > 0.f ? v3 : (__expf(v3) - 1.f);
        *(float2*)(outg + (size_t)R0 * DCAT + h * NHID + 8 * nt + 2 * q) =
            make_float2(v0, v1);
        *(float2*)(outg + (size_t)R1 * DCAT + h * NHID + 8 * nt + 2 * q) =
            make_float2(v2, v3);
    }
}

// ============================================================
// K3: xi = elu(hcat @ W_int^T + b_int) -> @ W_fus^T + b_fus -> log_softmax
// thread = (node, class). grid 192 x 256 thr.
// ============================================================
__global__ __launch_bounds__(256) void k3_out(const float* __restrict__ Wint,
                                              const float* __restrict__ bint,
                                              const float* __restrict__ Wfus,
                                              const float* __restrict__ bfus,
                                              float* __restrict__ out) {
    __shared__ float sWt[DCAT * 17];
    __shared__ float sWf[NCLASS * 49];
    __shared__ float sXi[16 * 48];
    __shared__ float sbi[NCLASS], sbf[NCLASS];
    const int t = threadIdx.x;
    for (int i = t; i < NCLASS * DCAT; i += 256) {
        int c = i >> 8, k = i & 255;
        sWt[k * 17 + c] = Wint[i];
    }
    for (int i = t; i < NCLASS * 48; i += 256) {
        int c = i / 48, j = i - c * 48;
        sWf[c * 49 + j] = Wfus[i];
    }
    if (t < NCLASS) { sbi[t] = bint[t]; sbf[t] = bfus[t]; }
    __syncthreads();

    const int nb = t >> 4, c = t & 15;
    const int n = blockIdx.x * 16 + nb;

#pragma unroll
    for (int g = 0; g < NGRAPH; g++) {
        const float* hp = d_hcat + ((size_t)g * N_NODES + n) * DCAT;
        float acc = 0.f;
#pragma unroll 8
        for (int k0 = 0; k0 < DCAT; k0 += 4) {
            float4 h4 = *(const float4*)(hp + k0);
            acc += h4.x * sWt[(k0 + 0) * 17 + c];
            acc += h4.y * sWt[(k0 + 1) * 17 + c];
            acc += h4.z * sWt[(k0 + 2) * 17 + c];
            acc += h4.w * sWt[(k0 + 3) * 17 + c];
        }
        float xv = acc + sbi[c];
        sXi[nb * 48 + g * 16 + c] = xv > 0.f ? xv : (__expf(xv) - 1.f);
    }
    __syncthreads();

    float o = sbf[c];
#pragma unroll
    for (int j = 0; j < 48; j++) o += sXi[nb * 48 + j] * sWf[c * 49 + j];

    float m = o;
#pragma unroll
    for (int off = 1; off < 16; off <<= 1)
        m = fmaxf(m, __shfl_xor_sync(0xffffffffu, m, off));
    float e = __expf(o - m), se = e;
#pragma unroll
    for (int off = 1; off < 16; off <<= 1)
        se += __shfl_xor_sync(0xffffffffu, se, off);
    out[(size_t)n * NCLASS + c] = o - m - __logf(se);
}

// ============================================================
// K4: l1 loss = mean |W_fus|
// ============================================================
__global__ void k4_loss(const float* __restrict__ Wfus, float* __restrict__ out) {
    __shared__ float s[256];
    const int t = threadIdx.x;
    float v = 0.f;
    for (int i = t; i < NCLASS * NCLASS * NGRAPH; i += 256) v += fabsf(Wfus[i]);
    s[t] = v;
    __syncthreads();
    for (int st = 128; st > 0; st >>= 1) {
        if (t < st) s[t] += s[t + st];
        __syncthreads();
    }
    if (t == 0) out[N_NODES * NCLASS] = s[0] / (float)(NCLASS * NCLASS * NGRAPH);
}

// ============================================================
extern "C" void kernel_launch(void* const* d_in, const int* in_sizes, int n_in,
                              void* d_out, int out_size) {
    const float* x    = (const float*)d_in[0];
    const int*   adj  = (const int*)  d_in[1];
    const float* W    = (const float*)d_in[2];
    const float* a    = (const float*)d_in[3];
    const float* Wint = (const float*)d_in[4];
    const float* bint = (const float*)d_in[5];
    const float* Wfus = (const float*)d_in[6];
    const float* bfus = (const float*)d_in[7];
    float* out = (float*)d_out;

    k0_pack<<<NGRAPH * N_NODES / 8, 256>>>(adj);
    k1_wh<<<dim3(N_NODES / 64, NGH), 128>>>(x, W, a);
    k2_attn<<<dim3(N_NODES / 64, NHEADS, NGRAPH), 128>>>();
    k3_out<<<N_NODES / 16, 256>>>(Wint, bint, Wfus, bfus, out);
    if (out_size > N_NODES * NCLASS)
        k4_loss<<<1, 256>>>(Wfus, out);
}

// round 11
// speedup vs baseline: 6.0522x; 1.0869x over previous
#include <cuda_runtime.h>
#include <math.h>
#include <stdint.h>

#define N_NODES 3072
#define F_IN 512
#define NHID 64
#define NHEADS 4
#define NGRAPH 3
#define NCLASS 16
#define NGH (NGRAPH * NHEADS)
#define DCAT (NHEADS * NHID)   // 256
#define ALPHA 0.2f

// -------- scratch (no allocations allowed) --------
__device__ uint32_t d_Whbf[NGH * 48 * 2048];                 // bf16x2, tile-swizzled
__device__ float2 d_ef1[NGH * N_NODES];                      // (e^f1, e^{0.2 f1})
__device__ float2 d_ef2[NGH * N_NODES];                      // (e^f2, e^{0.2 f2})
__device__ float d_hcat[NGRAPH * N_NODES * DCAT];            // [g][n][h*64+o]
__device__ unsigned long long d_abits[NGRAPH * N_NODES * 48]; // bitpacked adj

// ---------- helpers ----------
__device__ __forceinline__ uint32_t f2tf32(float f) {
    uint32_t u;
    asm("cvt.rna.tf32.f32 %0, %1;" : "=r"(u) : "f"(f));
    return u;
}
__device__ __forceinline__ uint32_t pkbf2(float lo, float hi) {
    uint32_t r;
    asm("cvt.rn.bf16x2.f32 %0, %1, %2;" : "=r"(r) : "f"(hi), "f"(lo));
    return r;
}
__device__ __forceinline__ void mma_tf32(float d[4], uint32_t a0, uint32_t a1,
                                         uint32_t a2, uint32_t a3,
                                         uint32_t b0, uint32_t b1) {
    asm volatile(
        "mma.sync.aligned.m16n8k8.row.col.f32.tf32.tf32.f32 "
        "{%0,%1,%2,%3},{%4,%5,%6,%7},{%8,%9},{%0,%1,%2,%3};\n"
        : "+f"(d[0]), "+f"(d[1]), "+f"(d[2]), "+f"(d[3])
        : "r"(a0), "r"(a1), "r"(a2), "r"(a3), "r"(b0), "r"(b1));
}
__device__ __forceinline__ void mma_bf16(float d[4], uint32_t a0, uint32_t a1,
                                         uint32_t a2, uint32_t a3,
                                         uint32_t b0, uint32_t b1) {
    asm volatile(
        "mma.sync.aligned.m16n8k16.row.col.f32.bf16.bf16.f32 "
        "{%0,%1,%2,%3},{%4,%5,%6,%7},{%8,%9},{%0,%1,%2,%3};\n"
        : "+f"(d[0]), "+f"(d[1]), "+f"(d[2]), "+f"(d[3])
        : "r"(a0), "r"(a1), "r"(a2), "r"(a3), "r"(b0), "r"(b1));
}
// word-granular swizzle: word (kp, n) of a [32|64]x64 word tile.
__device__ __forceinline__ int bswz(int k, int n) {
    return k * 64 + (n ^ ((k & 3) << 3));
}
__device__ __forceinline__ int aswz(int r, int c) {
    return r * 64 + (c ^ ((r & 3) << 3) ^ (r & 4));
}
// cp.async
__device__ __forceinline__ void cpa16(void* smem_dst, const void* gsrc) {
    uint32_t d = (uint32_t)__cvta_generic_to_shared(smem_dst);
    asm volatile("cp.async.ca.shared.global [%0], [%1], 16;\n" :: "r"(d), "l"(gsrc));
}
__device__ __forceinline__ void cpa_commit() {
    asm volatile("cp.async.commit_group;\n");
}
template <int NW> __device__ __forceinline__ void cpa_wait() {
    asm volatile("cp.async.wait_group %0;\n" :: "n"(NW));
}

// ============================================================
// K0: bitpack adj (int32 0/1 -> 64-bit masks). One warp per row.
// ============================================================
__global__ __launch_bounds__(256) void k0_pack(const int* __restrict__ adj) {
    const int row = blockIdx.x * 8 + (threadIdx.x >> 5);  // g*N + n
    const int lane = threadIdx.x & 31;
    const int* arow = adj + (size_t)row * N_NODES;
    unsigned long long* brow = d_abits + (size_t)row * 48;
    for (int j = 0; j < 48; j++) {
        unsigned lo = __ballot_sync(0xffffffffu, arow[j * 64 + lane] != 0);
        unsigned hi = __ballot_sync(0xffffffffu, arow[j * 64 + 32 + lane] != 0);
        if (lane == 0) brow[j] = ((unsigned long long)hi << 32) | lo;
    }
}

// ============================================================
// K1: Wh = x @ W via tf32 mma; epilogue fuses:
//   - f1/f2 row factors -> exp forms (d_ef1/d_ef2)
//   - bf16 pack + tile swizzle -> d_Whbf (k2-ready)
// grid (48, 12), 128 thr.
// ============================================================
__global__ __launch_bounds__(128) void k1_wh(const float* __restrict__ x,
                                             const float* __restrict__ W,
                                             const float* __restrict__ a) {
    __shared__ uint32_t As[64 * 64];
    __shared__ uint32_t Bs[64 * 64];
    __shared__ float sa[128];
    const int gh = blockIdx.y, n0 = blockIdx.x * 64;
    const int t = threadIdx.x, lane = t & 31, w = t >> 5;
    const int gi = lane >> 2, q = lane & 3;
    const float* Wg = W + (size_t)gh * F_IN * NHID;
    if (t < 128) sa[t] = a[gh * 128 + t];

    float acc[8][4];
#pragma unroll
    for (int nt = 0; nt < 8; nt++)
#pragma unroll
        for (int j = 0; j < 4; j++) acc[nt][j] = 0.f;

    for (int k0 = 0; k0 < F_IN; k0 += 64) {
        __syncthreads();
#pragma unroll
        for (int it = 0; it < 8; it++) {
            int idx = t + it * 128;
            int r = idx >> 4, c4 = (idx & 15) * 4;
            float4 v = *(const float4*)(x + (size_t)(n0 + r) * F_IN + k0 + c4);
            int o = aswz(r, c4);
            As[o] = f2tf32(v.x); As[o + 1] = f2tf32(v.y);
            As[o + 2] = f2tf32(v.z); As[o + 3] = f2tf32(v.w);
        }
#pragma unroll
        for (int it = 0; it < 8; it++) {
            int idx = t + it * 128;
            int k = idx >> 4, n4 = (idx & 15) * 4;
            float4 v = *(const float4*)(Wg + (size_t)(k0 + k) * NHID + n4);
            int o = bswz(k, n4);
            Bs[o] = f2tf32(v.x); Bs[o + 1] = f2tf32(v.y);
            Bs[o + 2] = f2tf32(v.z); Bs[o + 3] = f2tf32(v.w);
        }
        __syncthreads();
#pragma unroll
        for (int kt = 0; kt < 8; kt++) {
            uint32_t a0 = As[aswz(16 * w + gi,     8 * kt + q)];
            uint32_t a1 = As[aswz(16 * w + gi + 8, 8 * kt + q)];
            uint32_t a2 = As[aswz(16 * w + gi,     8 * kt + q + 4)];
            uint32_t a3 = As[aswz(16 * w + gi + 8, 8 * kt + q + 4)];
#pragma unroll
            for (int nt = 0; nt < 8; nt++) {
                uint32_t b0 = Bs[bswz(8 * kt + q,     8 * nt + gi)];
                uint32_t b1 = Bs[bswz(8 * kt + q + 4, 8 * nt + gi)];
                mma_tf32(acc[nt], a0, a1, a2, a3, b0, b1);
            }
        }
    }

    const int R0 = n0 + 16 * w + gi, R1 = R0 + 8;

    // ---- f1/f2 (full-precision fragments), then exp forms ----
    float p10 = 0.f, p20 = 0.f, p11 = 0.f, p21 = 0.f;
#pragma unroll
    for (int nt = 0; nt < 8; nt++) {
        int c0 = 8 * nt + 2 * q;
        p10 += acc[nt][0] * sa[c0]      + acc[nt][1] * sa[c0 + 1];
        p20 += acc[nt][0] * sa[64 + c0] + acc[nt][1] * sa[64 + c0 + 1];
        p11 += acc[nt][2] * sa[c0]      + acc[nt][3] * sa[c0 + 1];
        p21 += acc[nt][2] * sa[64 + c0] + acc[nt][3] * sa[64 + c0 + 1];
    }
#pragma unroll
    for (int off = 1; off < 4; off <<= 1) {
        p10 += __shfl_xor_sync(0xffffffffu, p10, off);
        p20 += __shfl_xor_sync(0xffffffffu, p20, off);
        p11 += __shfl_xor_sync(0xffffffffu, p11, off);
        p21 += __shfl_xor_sync(0xffffffffu, p21, off);
    }
    if (q == 0) {
        d_ef1[(size_t)gh * N_NODES + R0] = make_float2(__expf(p10), __expf(ALPHA * p10));
        d_ef2[(size_t)gh * N_NODES + R0] = make_float2(__expf(p20), __expf(ALPHA * p20));
        d_ef1[(size_t)gh * N_NODES + R1] = make_float2(__expf(p11), __expf(ALPHA * p11));
        d_ef2[(size_t)gh * N_NODES + R1] = make_float2(__expf(p21), __expf(ALPHA * p21));
    }

    // ---- bf16 pack, adjacent-row pairing via shfl, swizzled store ----
    uint32_t* dst = d_Whbf + ((size_t)gh * 48 + blockIdx.x) * 2048;
    const bool even = (gi & 1) == 0;
    const int kp = 8 * w + (gi >> 1) + (even ? 0 : 4);
#pragma unroll
    for (int nt = 0; nt < 8; nt++) {
        float o0 = __shfl_xor_sync(0xffffffffu, acc[nt][0], 4);
        float o1 = __shfl_xor_sync(0xffffffffu, acc[nt][1], 4);
        float o2 = __shfl_xor_sync(0xffffffffu, acc[nt][2], 4);
        float o3 = __shfl_xor_sync(0xffffffffu, acc[nt][3], 4);
        uint32_t w0, w1;
        if (even) { w0 = pkbf2(acc[nt][0], o0); w1 = pkbf2(acc[nt][1], o1); }
        else      { w0 = pkbf2(o2, acc[nt][2]); w1 = pkbf2(o3, acc[nt][3]); }
        int c = 8 * nt + 2 * q;
        int o = bswz(kp, c);
        *(uint2*)&dst[o] = make_uint2(w0, w1);
    }
}

// ============================================================
// K2: fused attention. exp(leaky(s)) = max(ea*eb, fa*fb) -- zero MUFU
// in the hot loop. cp.async double-buffered staging of pre-packed bf16 Wh.
// grid (48, NHEADS, NGRAPH), 128 thr.
// ============================================================
__global__ __launch_bounds__(128) void k2_attn() {
    __shared__ uint32_t Whs[2][2048];
    __shared__ float2 efs[2][64];
    const int g_ = blockIdx.z, h = blockIdx.y;
    const int gh = g_ * NHEADS + h;
    const int n0 = blockIdx.x * 64;
    const int t = threadIdx.x, lane = t & 31, w = t >> 5;
    const int gi = lane >> 2, q = lane & 3;
    const int qx = q << 3;
    const int R0 = n0 + 16 * w + gi, R1 = R0 + 8;

    const uint32_t* Wsrc = d_Whbf + (size_t)gh * 48 * 2048;
    const float2* ef2g = d_ef2 + (size_t)gh * N_NODES;
    const unsigned long long* bits0 = d_abits + ((size_t)g_ * N_NODES + R0) * 48;
    const unsigned long long* bits1 = d_abits + ((size_t)g_ * N_NODES + R1) * 48;
    const float2 ef1a = d_ef1[(size_t)gh * N_NODES + R0];
    const float2 ef1b = d_ef1[(size_t)gh * N_NODES + R1];
    const float ea0 = ef1a.x, fa0 = ef1a.y, ea1 = ef1b.x, fa1 = ef1b.y;

    int nxs[8];
#pragma unroll
    for (int nt = 0; nt < 8; nt++) nxs[nt] = (8 * nt + gi) ^ qx;

    float acc[8][4];
#pragma unroll
    for (int nt = 0; nt < 8; nt++)
#pragma unroll
        for (int j = 0; j < 4; j++) acc[nt][j] = 0.f;
    float rs0 = 0.f, rs1 = 0.f;

    // stage tile 0
    {
        const uint32_t* src = Wsrc;
#pragma unroll
        for (int it = 0; it < 4; it++)
            cpa16(&Whs[0][(t + it * 128) * 4], src + (t + it * 128) * 4);
        if (t < 32) cpa16(&efs[0][t * 2], ef2g + t * 2);
        cpa_commit();
    }

    for (int mt = 0; mt < 48; mt++) {
        const int buf = mt & 1;
        if (mt + 1 < 48) {
            const uint32_t* src = Wsrc + (size_t)(mt + 1) * 2048;
#pragma unroll
            for (int it = 0; it < 4; it++)
                cpa16(&Whs[buf ^ 1][(t + it * 128) * 4], src + (t + it * 128) * 4);
            if (t < 32) cpa16(&efs[buf ^ 1][t * 2], ef2g + (mt + 1) * 64 + t * 2);
            cpa_commit();
            cpa_wait<1>();
        } else {
            cpa_wait<0>();
        }
        __syncthreads();

        const uint32_t m0lo = (uint32_t)bits0[mt], m0hi = (uint32_t)(bits0[mt] >> 32);
        const uint32_t m1lo = (uint32_t)bits1[mt], m1hi = (uint32_t)(bits1[mt] >> 32);

#pragma unroll
        for (int kt = 0; kt < 4; kt++) {
            const int cb = 16 * kt + 2 * q;
            const float2 e0 = efs[buf][cb],     e1 = efs[buf][cb + 1];
            const float2 e8 = efs[buf][cb + 8], e9 = efs[buf][cb + 9];
            const uint32_t m0b = (kt < 2) ? (m0lo >> cb) : (m0hi >> (cb - 32));
            const uint32_t m1b = (kt < 2) ? (m1lo >> cb) : (m1hi >> (cb - 32));

            float p00 = fmaxf(ea0 * e0.x, fa0 * e0.y);
            float p01 = fmaxf(ea0 * e1.x, fa0 * e1.y);
            float p02 = fmaxf(ea0 * e8.x, fa0 * e8.y);
            float p03 = fmaxf(ea0 * e9.x, fa0 * e9.y);
            float p10 = fmaxf(ea1 * e0.x, fa1 * e0.y);
            float p11 = fmaxf(ea1 * e1.x, fa1 * e1.y);
            float p12 = fmaxf(ea1 * e8.x, fa1 * e8.y);
            float p13 = fmaxf(ea1 * e9.x, fa1 * e9.y);

            p00 = (m0b & 1u)     ? p00 : 0.f;
            p01 = (m0b & 2u)     ? p01 : 0.f;
            p02 = (m0b & 0x100u) ? p02 : 0.f;
            p03 = (m0b & 0x200u) ? p03 : 0.f;
            p10 = (m1b & 1u)     ? p10 : 0.f;
            p11 = (m1b & 2u)     ? p11 : 0.f;
            p12 = (m1b & 0x100u) ? p12 : 0.f;
            p13 = (m1b & 0x200u) ? p13 : 0.f;

            rs0 += (p00 + p01) + (p02 + p03);
            rs1 += (p10 + p11) + (p12 + p13);

            const uint32_t a0 = pkbf2(p00, p01);
            const uint32_t a1 = pkbf2(p10, p11);
            const uint32_t a2 = pkbf2(p02, p03);
            const uint32_t a3 = pkbf2(p12, p13);
            const int kb0 = (8 * kt + q) * 64;
            const int kb1 = kb0 + 256;
#pragma unroll
            for (int nt = 0; nt < 8; nt++) {
                uint32_t b0 = Whs[buf][kb0 + nxs[nt]];
                uint32_t b1 = Whs[buf][kb1 + nxs[nt]];
                mma_bf16(acc[nt], a0, a1, a2, a3, b0, b1);
            }
        }
        __syncthreads();
    }

    rs0 += __shfl_xor_sync(0xffffffffu, rs0, 1);
    rs0 += __shfl_xor_sync(0xffffffffu, rs0, 2);
    rs1 += __shfl_xor_sync(0xffffffffu, rs1, 1);
    rs1 += __shfl_xor_sync(0xffffffffu, rs1, 2);

    const float inv0 = 1.0f / rs0, inv1 = 1.0f / rs1;
    float* outg = d_hcat + (size_t)g_ * N_NODES * DCAT;
#pragma unroll
    for (int nt = 0; nt < 8; nt++) {
        float v0 = acc[nt][0] * inv0, v1 = acc[nt][1] * inv0;
        float v2 = acc[nt][2] * inv1, v3 = acc[nt][3] * inv1;
        v0 = v0 > 0.f ? v0 : (__expf(v0) - 1.f);
        v1 = v1 > 0.f ? v1 : (__expf(v1) - 1.f);
        v2 = v2 > 0.f ? v2 : (__expf(v2) - 1.f);
        v3 = v3 > 0.f ? v3 : (__expf(v3) - 1.f);
        *(float2*)(outg + (size_t)R0 * DCAT + h * NHID + 8 * nt + 2 * q) =
            make_float2(v0, v1);
        *(float2*)(outg + (size_t)R1 * DCAT + h * NHID + 8 * nt + 2 * q) =
            make_float2(v2, v3);
    }
}

// ============================================================
// K3: xi = elu(hcat @ W_int^T + b_int) -> @ W_fus^T + b_fus -> log_softmax
// thread = (node, class), natural-layout W_int (LDS.128, phase-conflict-free:
// bank=(4c+k0)%32), 4 independent FMA chains. 8 nodes/block, grid 384.
// ============================================================
__global__ __launch_bounds__(128) void k3_out(const float* __restrict__ Wint,
                                              const float* __restrict__ bint,
                                              const float* __restrict__ Wfus,
                                              const float* __restrict__ bfus,
                                              float* __restrict__ out) {
    __shared__ float sWi[NCLASS][260];               // natural [c][k], pad 260
    __shared__ float sWf[NCLASS * 49];
    __shared__ float sXi[8 * 48];
    __shared__ float sbi[NCLASS], sbf[NCLASS];
    const int t = threadIdx.x;
    for (int i = t; i < NCLASS * DCAT; i += 128) {
        int c = i >> 8, k = i & 255;
        sWi[c][k] = Wint[i];
    }
    for (int i = t; i < NCLASS * 48; i += 128) {
        int c = i / 48, j = i - c * 48;
        sWf[c * 49 + j] = Wfus[i];
    }
    if (t < NCLASS) { sbi[t] = bint[t]; sbf[t] = bfus[t]; }
    __syncthreads();

    const int nb = t >> 4, c = t & 15;
    const int n = blockIdx.x * 8 + nb;
    const float* wc = sWi[c];

#pragma unroll
    for (int g = 0; g < NGRAPH; g++) {
        const float* hp = d_hcat + ((size_t)g * N_NODES + n) * DCAT;
        float a0 = 0.f, a1 = 0.f, a2 = 0.f, a3 = 0.f;
#pragma unroll 4
        for (int k0 = 0; k0 < DCAT; k0 += 16) {
            float4 h0 = *(const float4*)(hp + k0);
            float4 h1 = *(const float4*)(hp + k0 + 4);
            float4 h2 = *(const float4*)(hp + k0 + 8);
            float4 h3 = *(const float4*)(hp + k0 + 12);
            float4 w0 = *(const float4*)(wc + k0);
            float4 w1 = *(const float4*)(wc + k0 + 4);
            float4 w2 = *(const float4*)(wc + k0 + 8);
            float4 w3 = *(const float4*)(wc + k0 + 12);
            a0 += h0.x * w0.x + h0.y * w0.y + h0.z * w0.z + h0.w * w0.w;
            a1 += h1.x * w1.x + h1.y * w1.y + h1.z * w1.z + h1.w * w1.w;
            a2 += h2.x * w2.x + h2.y * w2.y + h2.z * w2.z + h2.w * w2.w;
            a3 += h3.x * w3.x + h3.y * w3.y + h3.z * w3.z + h3.w * w3.w;
        }
        float xv = (a0 + a1) + (a2 + a3) + sbi[c];
        sXi[nb * 48 + g * 16 + c] = xv > 0.f ? xv : (__expf(xv) - 1.f);
    }
    __syncthreads();

    float o = sbf[c];
#pragma unroll
    for (int j = 0; j < 48; j++) o += sXi[nb * 48 + j] * sWf[c * 49 + j];

    float m = o;
#pragma unroll
    for (int off = 1; off < 16; off <<= 1)
        m = fmaxf(m, __shfl_xor_sync(0xffffffffu, m, off));
    float e = __expf(o - m), se = e;
#pragma unroll
    for (int off = 1; off < 16; off <<= 1)
        se += __shfl_xor_sync(0xffffffffu, se, off);
    out[(size_t)n * NCLASS + c] = o - m - __logf(se);
}

// ============================================================
// K4: l1 loss = mean |W_fus|
// ============================================================
__global__ void k4_loss(const float* __restrict__ Wfus, float* __restrict__ out) {
    __shared__ float s[256];
    const int t = threadIdx.x;
    float v = 0.f;
    for (int i = t; i < NCLASS * NCLASS * NGRAPH; i += 256) v += fabsf(Wfus[i]);
    s[t] = v;
    __syncthreads();
    for (int st = 128; st > 0; st >>= 1) {
        if (t < st) s[t] += s[t + st];
        __syncthreads();
    }
    if (t == 0) out[N_NODES * NCLASS] = s[0] / (float)(NCLASS * NCLASS * NGRAPH);
}

// ============================================================
extern "C" void kernel_launch(void* const* d_in, const int* in_sizes, int n_in,
                              void* d_out, int out_size) {
    const float* x    = (const float*)d_in[0];
    const int*   adj  = (const int*)  d_in[1];
    const float* W    = (const float*)d_in[2];
    const float* a    = (const float*)d_in[3];
    const float* Wint = (const float*)d_in[4];
    const float* bint = (const float*)d_in[5];
    const float* Wfus = (const float*)d_in[6];
    const float* bfus = (const float*)d_in[7];
    float* out = (float*)d_out;

    k0_pack<<<NGRAPH * N_NODES / 8, 256>>>(adj);
    k1_wh<<<dim3(N_NODES / 64, NGH), 128>>>(x, W, a);
    k2_attn<<<dim3(N_NODES / 64, NHEADS, NGRAPH), 128>>>();
    k3_out<<<N_NODES / 8, 128>>>(Wint, bint, Wfus, bfus, out);
    if (out_size > N_NODES * NCLASS)
        k4_loss<<<1, 256>>>(Wfus, out);
}